// round 7
// baseline (speedup 1.0000x reference)
#include <cuda_runtime.h>
#include <cuda_bf16.h>
#include <cstdint>

#define BATCH 4
#define NQ    4096
#define NK    4096
#define DIM   256
#define SCALE 0.17677669529663687f   // (256/8)^-0.5

#define BM 128
#define BN 64
#define NBLK (NK / BN)
#define THREADS 512

#define QK_STRIDE 264   // 256 + 8 pad (bf16) -> 528B rows, conflict-free LDSM
#define P_STRIDE  72    // 64 + 8 pad

// device-global scratch (no allocations allowed)
__device__ __nv_bfloat16 g_Qn[BATCH * NQ * DIM];
__device__ __nv_bfloat16 g_Kn[BATCH * NK * DIM];
__device__ __nv_bfloat16 g_Vb[BATCH * NK * DIM];
__device__ float         g_Vsum[BATCH * DIM];

// smem layout (bytes)
#define SQ_OFF  0u            // Q 128 x 264 bf16 = 67584
#define SK0_OFF 67584u        // K/V tiles 64 x 264 bf16 = 33792 each
#define SV0_OFF 101376u
#define SK1_OFF 135168u
#define SV1_OFF 168960u
#define SP_OFF  202752u       // P 128 x 72 bf16 = 18432
#define SL_OFF  221184u       // float[2][128] = 1024
#define SVS_OFF 222208u       // float[256]   = 1024
static const int SMEM_BYTES = 223232;

// ---------------------------------------------------------------- helpers
__device__ __forceinline__ uint32_t smem_u32(const void* p) {
    return (uint32_t)__cvta_generic_to_shared(p);
}

#define LDSM_X4(r0, r1, r2, r3, addr)                                              \
    asm volatile("ldmatrix.sync.aligned.m8n8.x4.shared.b16 {%0,%1,%2,%3},[%4];"    \
                 : "=r"(r0), "=r"(r1), "=r"(r2), "=r"(r3) : "r"(addr))

#define LDSM_X4_T(r0, r1, r2, r3, addr)                                                 \
    asm volatile("ldmatrix.sync.aligned.m8n8.x4.trans.shared.b16 {%0,%1,%2,%3},[%4];"   \
                 : "=r"(r0), "=r"(r1), "=r"(r2), "=r"(r3) : "r"(addr))

#define MMA16816(d, a0, a1, a2, a3, b0, b1)                                        \
    asm volatile("mma.sync.aligned.m16n8k16.row.col.f32.bf16.bf16.f32 "            \
                 "{%0,%1,%2,%3},{%4,%5,%6,%7},{%8,%9},{%0,%1,%2,%3};"              \
                 : "+f"(d[0]), "+f"(d[1]), "+f"(d[2]), "+f"(d[3])                  \
                 : "r"(a0), "r"(a1), "r"(a2), "r"(a3), "r"(b0), "r"(b1))

__device__ __forceinline__ void cp16(uint32_t s, const void* g) {
    asm volatile("cp.async.cg.shared.global [%0], [%1], 16;" :: "r"(s), "l"(g));
}
#define CP_COMMIT() asm volatile("cp.async.commit_group;" ::: "memory")
#define CP_WAIT(n)  asm volatile("cp.async.wait_group %0;" :: "n"(n) : "memory")
#define BAR_SYNC(id, cnt) asm volatile("bar.sync %0, %1;" :: "r"(id), "r"(cnt) : "memory")

// ---------------------------------------------------------------- prep kernels
__global__ void zero_vsum_kernel() { g_Vsum[threadIdx.x] = 0.0f; }

__global__ void vprep_kernel(const float* __restrict__ v) {
    int b = blockIdx.y, chunk = blockIdx.x, d = threadIdx.x;
    size_t base = ((size_t)b * NK + (size_t)chunk * 128) * DIM + d;
    float sum = 0.0f;
    for (int r = 0; r < 128; r++) {
        float x = v[base + (size_t)r * DIM];
        sum += x;
        g_Vb[base + (size_t)r * DIM] = __float2bfloat16(x);
    }
    atomicAdd(&g_Vsum[b * DIM + d], sum);
}

__global__ void normalize_kernel(const float* __restrict__ q, const float* __restrict__ k) {
    int gw = (blockIdx.x * blockDim.x + threadIdx.x) >> 5;
    int lane = threadIdx.x & 31;
    const float* src;
    __nv_bfloat16* dst;
    int row;
    if (gw < BATCH * NQ) { src = q; dst = g_Qn; row = gw; }
    else                 { src = k; dst = g_Kn; row = gw - BATCH * NQ; }

    const float4* p = (const float4*)(src + (size_t)row * DIM);
    float4 v0 = p[lane];
    float4 v1 = p[lane + 32];
    float ss = v0.x * v0.x + v0.y * v0.y + v0.z * v0.z + v0.w * v0.w
             + v1.x * v1.x + v1.y * v1.y + v1.z * v1.z + v1.w * v1.w;
#pragma unroll
    for (int off = 16; off > 0; off >>= 1) ss += __shfl_xor_sync(0xffffffffu, ss, off);
    float sc = 1.0f / fmaxf(sqrtf(ss), 1e-12f);

    __nv_bfloat162* drow = (__nv_bfloat162*)(dst + (size_t)row * DIM);
    drow[lane * 2 + 0]      = __floats2bfloat162_rn(v0.x * sc, v0.y * sc);
    drow[lane * 2 + 1]      = __floats2bfloat162_rn(v0.z * sc, v0.w * sc);
    drow[64 + lane * 2 + 0] = __floats2bfloat162_rn(v1.x * sc, v1.y * sc);
    drow[64 + lane * 2 + 1] = __floats2bfloat162_rn(v1.z * sc, v1.w * sc);
}

// ---------------------------------------------------------------- fused attention
// out = (Vsum + sum_j (exp(s_j)-1) v_j) / (NK + sum_j (exp(s_j)-1)),  |s| <= SCALE.
// 16 warps; pair (p, p+8) shares 16 query rows: each computes S for 32 keys,
// exchanges P halves through smem (pairwise named barrier), then computes PV
// for 128 output columns over all 64 keys.
extern "C" __global__ void __launch_bounds__(THREADS, 1)
flash_kernel(float* __restrict__ out) {
    extern __shared__ __align__(128) char smem[];
    const uint32_t sb = smem_u32(smem);
    const int b  = blockIdx.y;
    const int q0 = blockIdx.x * BM;
    const int tid = threadIdx.x, lane = tid & 31, wid = tid >> 5;
    const int p = wid & 7;     // pair id: rows p*16..p*16+15
    const int h = wid >> 3;    // half id: QK keys h*32..; PV cols h*128..
    const int g = lane >> 3;

    float* sL  = (float*)(smem + SL_OFF);    // [2][128]
    float* sVS = (float*)(smem + SVS_OFF);

    // ---- load Q tile ----
    const uint4* gq = (const uint4*)(g_Qn + ((size_t)(b * NQ + q0)) * DIM);
    __nv_bfloat16* sQ = (__nv_bfloat16*)(smem + SQ_OFF);
    for (int i = tid; i < BM * 32; i += THREADS) {
        int r = i >> 5, c = i & 31;
        *(uint4*)(sQ + r * QK_STRIDE + c * 8) = gq[i];
    }
    if (tid < DIM) sVS[tid] = g_Vsum[b * DIM + tid];

    const char* gK = (const char*)(g_Kn + (size_t)b * NK * DIM);
    const char* gV = (const char*)(g_Vb + (size_t)b * NK * DIM);

    // prefetch block 0
    for (int i = tid; i < 4096; i += THREADS) {
        int r = (i >> 5) & 63, c = i & 31;
        if (i < 2048) cp16(sb + SK0_OFF + r * 528 + c * 16, gK + r * 512 + c * 16);
        else          cp16(sb + SV0_OFF + r * 528 + c * 16, gV + r * 512 + c * 16);
    }
    CP_COMMIT();

    // per-warp addresses
    const uint32_t aQ = sb + SQ_OFF +
        (uint32_t)(((p * 16 + (lane & 15)) * QK_STRIDE + (lane >> 4) * 8) * 2);
    // K B-operand: keys h*32 + kt*16
    const uint32_t bKrel = (uint32_t)(((h * 32 + (g >> 1) * 8 + (lane & 7)) * QK_STRIDE
                                      + (g & 1) * 8) * 2);
    // P smem: own-half store / partner-half load
    __nv_bfloat16* sP = (__nv_bfloat16*)(smem + SP_OFF);
    const int prow = p * 16 + (lane >> 2);
    const int pcolW = h * 32 + 2 * (lane & 3);
    const uint32_t aPpart = sb + SP_OFF +
        (uint32_t)(((p * 16 + (lane & 15)) * P_STRIDE + (1 - h) * 32 + (lane >> 4) * 8) * 2);
    // V B-operand: cols h*128
    const uint32_t bVrel = (uint32_t)((((g & 1) * 8 + (lane & 7)) * QK_STRIDE
                                      + h * 128 + (g >> 1) * 8) * 2);

    float oAcc[16][4];
#pragma unroll
    for (int a = 0; a < 16; a++)
#pragma unroll
        for (int j = 0; j < 4; j++) oAcc[a][j] = 0.0f;

    float eLo = 0.0f, eHi = 0.0f;   // partial row sums over this warp's 32 keys

    for (int kb = 0; kb < NBLK; kb++) {
        const uint32_t skb = (kb & 1) ? SK1_OFF : SK0_OFF;
        const uint32_t svb = (kb & 1) ? SV1_OFF : SV0_OFF;

        CP_WAIT(0);        // buffer kb landed
        __syncthreads();   // all warps done reading the other buffer (PV of kb-1)

        if (kb + 1 < NBLK) {
            const uint32_t skn = (kb & 1) ? SK0_OFF : SK1_OFF;
            const uint32_t svn = (kb & 1) ? SV0_OFF : SV1_OFF;
            const char* gKn = gK + (size_t)(kb + 1) * BN * 512;
            const char* gVn = gV + (size_t)(kb + 1) * BN * 512;
            for (int i = tid; i < 4096; i += THREADS) {
                int r = (i >> 5) & 63, c = i & 31;
                if (i < 2048) cp16(sb + skn + r * 528 + c * 16, gKn + r * 512 + c * 16);
                else          cp16(sb + svn + r * 528 + c * 16, gVn + r * 512 + c * 16);
            }
            CP_COMMIT();
        }

        // ---- S = Q @ K^T : 16 rows x 32 keys (this warp's half) ----
        float sAcc[4][4];
#pragma unroll
        for (int a = 0; a < 4; a++)
#pragma unroll
            for (int j = 0; j < 4; j++) sAcc[a][j] = 0.0f;

        const uint32_t bK = sb + skb + bKrel;
#pragma unroll
        for (int ks = 0; ks < 16; ks++) {
            uint32_t a0, a1, a2, a3;
            LDSM_X4(a0, a1, a2, a3, aQ + ks * 32);
#pragma unroll
            for (int kt = 0; kt < 2; kt++) {
                uint32_t b0, b1, b2, b3;
                LDSM_X4(b0, b1, b2, b3, bK + kt * (16 * QK_STRIDE * 2) + ks * 32);
                MMA16816(sAcc[2 * kt],     a0, a1, a2, a3, b0, b1);
                MMA16816(sAcc[2 * kt + 1], a0, a1, a2, a3, b2, b3);
            }
        }

        // ---- e = exp(s*SCALE)-1; partial row sums; pack own P half ----
        uint32_t pAll[4][4];   // A-frags over keys 0..63 (4 k-steps)
#pragma unroll
        for (int a = 0; a < 4; a++) {
#pragma unroll
            for (int j = 0; j < 4; j++)
                sAcc[a][j] = __expf(sAcc[a][j] * SCALE) - 1.0f;
            eLo += sAcc[a][0] + sAcc[a][1];
            eHi += sAcc[a][2] + sAcc[a][3];
        }
#pragma unroll
        for (int kg = 0; kg < 2; kg++) {
            __nv_bfloat162 t0 = __floats2bfloat162_rn(sAcc[2 * kg][0], sAcc[2 * kg][1]);
            __nv_bfloat162 t1 = __floats2bfloat162_rn(sAcc[2 * kg][2], sAcc[2 * kg][3]);
            __nv_bfloat162 t2 = __floats2bfloat162_rn(sAcc[2 * kg + 1][0], sAcc[2 * kg + 1][1]);
            __nv_bfloat162 t3 = __floats2bfloat162_rn(sAcc[2 * kg + 1][2], sAcc[2 * kg + 1][3]);
            const int kk = h * 2 + kg;            // own half occupies k-steps h*2, h*2+1
            pAll[kk][0] = *(uint32_t*)&t0;
            pAll[kk][1] = *(uint32_t*)&t1;
            pAll[kk][2] = *(uint32_t*)&t2;
            pAll[kk][3] = *(uint32_t*)&t3;
        }
        // store own half to P smem for the partner
        {
#pragma unroll
            for (int a = 0; a < 4; a++) {
                *(__nv_bfloat162*)(sP + prow * P_STRIDE + pcolW + a * 8) =
                    __floats2bfloat162_rn(sAcc[a][0], sAcc[a][1]);
                *(__nv_bfloat162*)(sP + (prow + 8) * P_STRIDE + pcolW + a * 8) =
                    __floats2bfloat162_rn(sAcc[a][2], sAcc[a][3]);
            }
        }
        BAR_SYNC(p + 1, 64);   // pair barrier: partner's P half visible

        // load partner's half (k-steps (1-h)*2, (1-h)*2+1)
        {
            const int kk = (1 - h) * 2;
            LDSM_X4(pAll[kk][0], pAll[kk][1], pAll[kk][2], pAll[kk][3], aPpart);
            LDSM_X4(pAll[kk + 1][0], pAll[kk + 1][1], pAll[kk + 1][2], pAll[kk + 1][3],
                    aPpart + 32);
        }

        // ---- O += P @ V : 16 rows x 128 cols (this warp's half), 64 keys ----
        const uint32_t bV = sb + svb + bVrel;
#pragma unroll
        for (int kk = 0; kk < 4; kk++) {
            const uint32_t vb = bV + kk * (16 * QK_STRIDE * 2);
#pragma unroll
            for (int cg = 0; cg < 8; cg++) {
                uint32_t v0, v1, v2, v3;
                LDSM_X4_T(v0, v1, v2, v3, vb + cg * 32);
                MMA16816(oAcc[cg * 2],
                         pAll[kk][0], pAll[kk][1], pAll[kk][2], pAll[kk][3], v0, v1);
                MMA16816(oAcc[cg * 2 + 1],
                         pAll[kk][0], pAll[kk][1], pAll[kk][2], pAll[kk][3], v2, v3);
            }
        }
    }

    // ---- combine row sums across the pair ----
    eLo += __shfl_xor_sync(0xffffffffu, eLo, 1);
    eLo += __shfl_xor_sync(0xffffffffu, eLo, 2);
    eHi += __shfl_xor_sync(0xffffffffu, eHi, 1);
    eHi += __shfl_xor_sync(0xffffffffu, eHi, 2);
    if ((lane & 3) == 0) {
        sL[h * 128 + p * 16 + (lane >> 2)] = eLo;
        sL[h * 128 + p * 16 + 8 + (lane >> 2)] = eHi;
    }
    __syncthreads();

    const int r1 = p * 16 + (lane >> 2);
    const float inv1 = 1.0f / ((float)NK + sL[r1] + sL[128 + r1]);
    const float inv2 = 1.0f / ((float)NK + sL[r1 + 8] + sL[128 + r1 + 8]);

    // ---- writeout: rows r1/r1+8, cols h*128 .. +127 ----
    float* op = out + ((size_t)(b * NQ + q0 + r1)) * DIM;
#pragma unroll
    for (int cg = 0; cg < 8; cg++) {
#pragma unroll
        for (int hh = 0; hh < 2; hh++) {
            const int idx = cg * 2 + hh;
            const int c = h * 128 + cg * 16 + hh * 8 + 2 * (lane & 3);
            float vs0 = sVS[c], vs1 = sVS[c + 1];
            float* acc = oAcc[idx];
            *(float2*)(op + c) =
                make_float2((vs0 + acc[0]) * inv1, (vs1 + acc[1]) * inv1);
            *(float2*)(op + 8 * DIM + c) =
                make_float2((vs0 + acc[2]) * inv2, (vs1 + acc[3]) * inv2);
        }
    }
}

// ---------------------------------------------------------------- launch
extern "C" void kernel_launch(void* const* d_in, const int* in_sizes, int n_in,
                              void* d_out, int out_size) {
    const float* q = (const float*)d_in[0];
    const float* k = (const float*)d_in[1];
    const float* v = (const float*)d_in[2];
    float* out = (float*)d_out;

    cudaFuncSetAttribute(flash_kernel, cudaFuncAttributeMaxDynamicSharedMemorySize, SMEM_BYTES);

    zero_vsum_kernel<<<1, BATCH * DIM>>>();
    vprep_kernel<<<dim3(NK / 128, BATCH), 256>>>(v);
    normalize_kernel<<<(2 * BATCH * NQ) / 8, 256>>>(q, k);
    flash_kernel<<<dim3(NQ / BM, BATCH), THREADS, SMEM_BYTES>>>(out);
}

// round 10
// speedup vs baseline: 1.3571x; 1.3571x over previous
#include <cuda_runtime.h>
#include <cuda_bf16.h>
#include <cstdint>

#define BATCH 4
#define NQ    4096
#define NK    4096
#define DIM   256
#define SCALE 0.17677669529663687f   // (256/8)^-0.5

#define BM 128
#define BN 64
#define NBLK (NK / BN)
#define THREADS 256

// device-global scratch (no allocations allowed)
__device__ __nv_bfloat16 g_Qn[BATCH * NQ * DIM];
__device__ __nv_bfloat16 g_Kn[BATCH * NK * DIM];
__device__ __nv_bfloat16 g_Vb[BATCH * NK * DIM];
__device__ float         g_Vsum[BATCH * DIM];

// smem layout (bytes) — XOR-swizzled tiles, 512B rows (no padding)
#define SQ_OFF  0u            // Q 128 x 256 bf16 = 65536
#define SK0_OFF 65536u        // K/V tiles 64 x 256 bf16 = 32768 each
#define SV0_OFF 98304u
#define SK1_OFF 131072u
#define SV1_OFF 163840u
#define SP_OFF  196608u       // P 128 x 64 bf16 = 16384 (128B rows)
#define SVS_OFF 212992u       // float[256]
#define SL_OFF  214016u       // float[2][128]
static const int SMEM_BYTES = 215040;

// ---------------------------------------------------------------- helpers
__device__ __forceinline__ uint32_t smem_u32(const void* p) {
    return (uint32_t)__cvta_generic_to_shared(p);
}

#define LDSM_X4(r0, r1, r2, r3, addr)                                              \
    asm volatile("ldmatrix.sync.aligned.m8n8.x4.shared.b16 {%0,%1,%2,%3},[%4];"    \
                 : "=r"(r0), "=r"(r1), "=r"(r2), "=r"(r3) : "r"(addr))

#define LDSM_X4_T(r0, r1, r2, r3, addr)                                                 \
    asm volatile("ldmatrix.sync.aligned.m8n8.x4.trans.shared.b16 {%0,%1,%2,%3},[%4];"   \
                 : "=r"(r0), "=r"(r1), "=r"(r2), "=r"(r3) : "r"(addr))

#define MMA16816(d, a0, a1, a2, a3, b0, b1)                                        \
    asm volatile("mma.sync.aligned.m16n8k16.row.col.f32.bf16.bf16.f32 "            \
                 "{%0,%1,%2,%3},{%4,%5,%6,%7},{%8,%9},{%0,%1,%2,%3};"              \
                 : "+f"(d[0]), "+f"(d[1]), "+f"(d[2]), "+f"(d[3])                  \
                 : "r"(a0), "r"(a1), "r"(a2), "r"(a3), "r"(b0), "r"(b1))

__device__ __forceinline__ void cp16(uint32_t s, const void* g) {
    asm volatile("cp.async.cg.shared.global [%0], [%1], 16;" :: "r"(s), "l"(g));
}
#define CP_COMMIT() asm volatile("cp.async.commit_group;" ::: "memory")
#define CP_WAIT(n)  asm volatile("cp.async.wait_group %0;" :: "n"(n) : "memory")

// ---------------------------------------------------------------- prep kernels
__global__ void zero_vsum_kernel() { g_Vsum[threadIdx.x] = 0.0f; }

__global__ void vprep_kernel(const float* __restrict__ v) {
    int b = blockIdx.y, chunk = blockIdx.x, d = threadIdx.x;
    size_t base = ((size_t)b * NK + (size_t)chunk * 128) * DIM + d;
    float sum = 0.0f;
    for (int r = 0; r < 128; r++) {
        float x = v[base + (size_t)r * DIM];
        sum += x;
        g_Vb[base + (size_t)r * DIM] = __float2bfloat16(x);
    }
    atomicAdd(&g_Vsum[b * DIM + d], sum);
}

__global__ void normalize_kernel(const float* __restrict__ q, const float* __restrict__ k) {
    int gw = (blockIdx.x * blockDim.x + threadIdx.x) >> 5;
    int lane = threadIdx.x & 31;
    const float* src;
    __nv_bfloat16* dst;
    int row;
    if (gw < BATCH * NQ) { src = q; dst = g_Qn; row = gw; }
    else                 { src = k; dst = g_Kn; row = gw - BATCH * NQ; }

    const float4* p = (const float4*)(src + (size_t)row * DIM);
    float4 v0 = p[lane];
    float4 v1 = p[lane + 32];
    float ss = v0.x * v0.x + v0.y * v0.y + v0.z * v0.z + v0.w * v0.w
             + v1.x * v1.x + v1.y * v1.y + v1.z * v1.z + v1.w * v1.w;
#pragma unroll
    for (int off = 16; off > 0; off >>= 1) ss += __shfl_xor_sync(0xffffffffu, ss, off);
    float sc = 1.0f / fmaxf(sqrtf(ss), 1e-12f);

    __nv_bfloat162* drow = (__nv_bfloat162*)(dst + (size_t)row * DIM);
    drow[lane * 2 + 0]      = __floats2bfloat162_rn(v0.x * sc, v0.y * sc);
    drow[lane * 2 + 1]      = __floats2bfloat162_rn(v0.z * sc, v0.w * sc);
    drow[64 + lane * 2 + 0] = __floats2bfloat162_rn(v1.x * sc, v1.y * sc);
    drow[64 + lane * 2 + 1] = __floats2bfloat162_rn(v1.z * sc, v1.w * sc);
}

// ---------------------------------------------------------------- fused attention
// out = (Vsum + sum_j (exp(s_j)-1) v_j) / (NK + sum_j (exp(s_j)-1)),  |s| <= SCALE.
// 8 warps: QK = 4 row-groups x 2 key-halves (32 rows x 32 keys per warp);
// P exchanged through swizzled smem; PV = 4 row-groups x 2 col-halves
// (32 rows x 128 cols per warp). Two barriers per key block.
extern "C" __global__ void __launch_bounds__(THREADS, 1)
flash_kernel(float* __restrict__ out) {
    extern __shared__ __align__(128) char smem[];
    const uint32_t sb = smem_u32(smem);
    const int b  = blockIdx.y;
    const int q0 = blockIdx.x * BM;
    const int tid = threadIdx.x, lane = tid & 31, wid = tid >> 5;
    const int rg = wid >> 1;       // row group: rows rg*32 .. +31
    const int hf = wid & 1;        // QK: keys hf*32.. ; PV: cols hf*128..
    const int g = lane >> 3;
    const int xs = lane & 7;       // swizzle XOR (== row&7 for all our patterns)

    float* sVS = (float*)(smem + SVS_OFF);
    float* sL  = (float*)(smem + SL_OFF);    // [2][128]

    // ---- load Q tile (swizzled) ----
    const uint4* gq = (const uint4*)(g_Qn + ((size_t)(b * NQ + q0)) * DIM);
    for (int i = tid; i < BM * 32; i += THREADS) {
        int r = i >> 5, c = i & 31;
        *(uint4*)(smem + SQ_OFF + r * 512 + ((c ^ (r & 7)) * 16)) = gq[i];
    }
    if (tid < DIM) sVS[tid] = g_Vsum[b * DIM + tid];

    const char* gK = (const char*)(g_Kn + (size_t)b * NK * DIM);
    const char* gV = (const char*)(g_Vb + (size_t)b * NK * DIM);

    // prefetch block 0
    for (int i = tid; i < 4096; i += THREADS) {
        int r = (i >> 5) & 63, c = i & 31;
        uint32_t dst = r * 512 + ((c ^ (r & 7)) * 16);
        if (i < 2048) cp16(sb + SK0_OFF + dst, gK + r * 512 + c * 16);
        else          cp16(sb + SV0_OFF + dst, gV + r * 512 + c * 16);
    }
    CP_COMMIT();

    // per-warp base addresses
    // QK A (Q): row = rg*32 + m*16 + (lane&15), chunk = ks*2 + (lane>>4)
    const uint32_t aQbase = sb + SQ_OFF + (uint32_t)((rg * 32 + (lane & 15)) * 512);
    const int qch = (lane >> 4);
    // QK B (K): row = hf*32 + kt*16 + (g>>1)*8 + (lane&7), chunk = ks*2 + (g&1)
    const uint32_t bKrow = (uint32_t)((hf * 32 + (g >> 1) * 8 + (lane & 7)) * 512);
    const int kch = (g & 1);
    // P store: row = rg*32 + m*16 + (lane>>2) (+8), chunk = hf*4 + kt4, ^ (lane>>2)
    const int prQuad = lane >> 2;
    // P A-frag: row = rg*32 + m*16 + (lane&15), chunk = kk*2 + (lane>>4)
    const uint32_t aPbase = sb + SP_OFF + (uint32_t)((rg * 32 + (lane & 15)) * 128);
    // PV B (V, trans): row = kk*16 + (g&1)*8 + (lane&7), chunk = hf*16 + cg*2 + (g>>1)
    const uint32_t bVrow = (uint32_t)(((g & 1) * 8 + (lane & 7)) * 512);

    float oAcc[32][4];
#pragma unroll
    for (int a = 0; a < 32; a++)
#pragma unroll
        for (int j = 0; j < 4; j++) oAcc[a][j] = 0.0f;

    float eL[2] = {0.0f, 0.0f}, eH[2] = {0.0f, 0.0f};

    for (int kb = 0; kb < NBLK; kb++) {
        const uint32_t skb = (kb & 1) ? SK1_OFF : SK0_OFF;
        const uint32_t svb = (kb & 1) ? SV1_OFF : SV0_OFF;

        CP_WAIT(0);        // buffer kb landed
        __syncthreads();   // visible to all; PV(kb-1)+P(kb-1) reads complete

        if (kb + 1 < NBLK) {
            const uint32_t skn = (kb & 1) ? SK0_OFF : SK1_OFF;
            const uint32_t svn = (kb & 1) ? SV0_OFF : SV1_OFF;
            const char* gKn = gK + (size_t)(kb + 1) * BN * 512;
            const char* gVn = gV + (size_t)(kb + 1) * BN * 512;
            for (int i = tid; i < 4096; i += THREADS) {
                int r = (i >> 5) & 63, c = i & 31;
                uint32_t dst = r * 512 + ((c ^ (r & 7)) * 16);
                if (i < 2048) cp16(sb + skn + dst, gKn + r * 512 + c * 16);
                else          cp16(sb + svn + dst, gVn + r * 512 + c * 16);
            }
            CP_COMMIT();
        }

        // ---- S = Q @ K^T : 32 rows x 32 keys per warp ----
        float sAcc[2][4][4];
#pragma unroll
        for (int m = 0; m < 2; m++)
#pragma unroll
            for (int a = 0; a < 4; a++)
#pragma unroll
                for (int j = 0; j < 4; j++) sAcc[m][a][j] = 0.0f;

#pragma unroll
        for (int ks = 0; ks < 16; ks++) {
            uint32_t qa0[4], qa1[4];
            const uint32_t qoff = (uint32_t)((((ks * 2 + qch) ^ xs)) * 16);
            LDSM_X4(qa0[0], qa0[1], qa0[2], qa0[3], aQbase + qoff);
            LDSM_X4(qa1[0], qa1[1], qa1[2], qa1[3], aQbase + 16 * 512 + qoff);
            const uint32_t koff = (uint32_t)((((ks * 2 + kch) ^ xs)) * 16);
#pragma unroll
            for (int kt = 0; kt < 2; kt++) {
                uint32_t b0, b1, b2, b3;
                LDSM_X4(b0, b1, b2, b3, sb + skb + bKrow + kt * (16 * 512) + koff);
                MMA16816(sAcc[0][kt * 2],     qa0[0], qa0[1], qa0[2], qa0[3], b0, b1);
                MMA16816(sAcc[0][kt * 2 + 1], qa0[0], qa0[1], qa0[2], qa0[3], b2, b3);
                MMA16816(sAcc[1][kt * 2],     qa1[0], qa1[1], qa1[2], qa1[3], b0, b1);
                MMA16816(sAcc[1][kt * 2 + 1], qa1[0], qa1[1], qa1[2], qa1[3], b2, b3);
            }
        }

        // ---- e = exp(s*SCALE)-1; partial row sums; P -> smem (swizzled) ----
#pragma unroll
        for (int m = 0; m < 2; m++) {
#pragma unroll
            for (int a = 0; a < 4; a++) {
#pragma unroll
                for (int j = 0; j < 4; j++)
                    sAcc[m][a][j] = __expf(sAcc[m][a][j] * SCALE) - 1.0f;
                eL[m] += sAcc[m][a][0] + sAcc[m][a][1];
                eH[m] += sAcc[m][a][2] + sAcc[m][a][3];
            }
#pragma unroll
            for (int a = 0; a < 4; a++) {
                const uint32_t pr = (uint32_t)(rg * 32 + m * 16 + prQuad);
                const uint32_t addr = sb + SP_OFF + pr * 128 +
                    (uint32_t)((((hf * 4 + a) ^ prQuad)) * 16) + (lane & 3) * 4;
                __nv_bfloat162 t0 = __floats2bfloat162_rn(sAcc[m][a][0], sAcc[m][a][1]);
                __nv_bfloat162 t1 = __floats2bfloat162_rn(sAcc[m][a][2], sAcc[m][a][3]);
                asm volatile("st.shared.b32 [%0], %1;" :: "r"(addr), "r"(*(uint32_t*)&t0));
                asm volatile("st.shared.b32 [%0], %1;" :: "r"(addr + 8 * 128), "r"(*(uint32_t*)&t1));
            }
        }
        __syncthreads();   // P complete

        // ---- O += P @ V : 32 rows x 128 cols per warp, 64 keys ----
#pragma unroll
        for (int kk = 0; kk < 4; kk++) {
            uint32_t pa0[4], pa1[4];
            const uint32_t poff = (uint32_t)((((kk * 2 + qch) ^ xs)) * 16);
            LDSM_X4(pa0[0], pa0[1], pa0[2], pa0[3], aPbase + poff);
            LDSM_X4(pa1[0], pa1[1], pa1[2], pa1[3], aPbase + 16 * 128 + poff);
            const uint32_t vrow = sb + svb + bVrow + (uint32_t)(kk * 16 * 512);
#pragma unroll
            for (int cg = 0; cg < 8; cg++) {
                uint32_t v0, v1, v2, v3;
                const int cc = hf * 16 + cg * 2 + (g >> 1);
                LDSM_X4_T(v0, v1, v2, v3, vrow + (uint32_t)(((cc ^ xs)) * 16));
                MMA16816(oAcc[cg * 2],          pa0[0], pa0[1], pa0[2], pa0[3], v0, v1);
                MMA16816(oAcc[cg * 2 + 1],      pa0[0], pa0[1], pa0[2], pa0[3], v2, v3);
                MMA16816(oAcc[16 + cg * 2],     pa1[0], pa1[1], pa1[2], pa1[3], v0, v1);
                MMA16816(oAcc[16 + cg * 2 + 1], pa1[0], pa1[1], pa1[2], pa1[3], v2, v3);
            }
        }
    }

    // ---- finalize row sums ----
#pragma unroll
    for (int m = 0; m < 2; m++) {
        eL[m] += __shfl_xor_sync(0xffffffffu, eL[m], 1);
        eL[m] += __shfl_xor_sync(0xffffffffu, eL[m], 2);
        eH[m] += __shfl_xor_sync(0xffffffffu, eH[m], 1);
        eH[m] += __shfl_xor_sync(0xffffffffu, eH[m], 2);
    }
    if ((lane & 3) == 0) {
        const int r0 = rg * 32 + (lane >> 2);
        sL[hf * 128 + r0]      = eL[0];
        sL[hf * 128 + r0 + 8]  = eH[0];
        sL[hf * 128 + r0 + 16] = eL[1];
        sL[hf * 128 + r0 + 24] = eH[1];
    }
    __syncthreads();

    // ---- writeout: rows rg*32 + m*16 + quad (+8), cols hf*128 .. +127 ----
    float* opb = out + ((size_t)(b * NQ + q0)) * DIM;
#pragma unroll
    for (int m = 0; m < 2; m++) {
        const int r1 = rg * 32 + m * 16 + (lane >> 2);
        const float inv1 = 1.0f / ((float)NK + sL[r1] + sL[128 + r1]);
        const float inv2 = 1.0f / ((float)NK + sL[r1 + 8] + sL[128 + r1 + 8]);
        float* op = opb + (size_t)r1 * DIM;
#pragma unroll
        for (int cg = 0; cg < 16; cg++) {
            const int c = hf * 128 + cg * 8 + 2 * (lane & 3);
            float vs0 = sVS[c], vs1 = sVS[c + 1];
            float* acc = oAcc[m * 16 + cg];
            *(float2*)(op + c) =
                make_float2((vs0 + acc[0]) * inv1, (vs1 + acc[1]) * inv1);
            *(float2*)(op + 8 * DIM + c) =
                make_float2((vs0 + acc[2]) * inv2, (vs1 + acc[3]) * inv2);
        }
    }
}

// ---------------------------------------------------------------- launch
extern "C" void kernel_launch(void* const* d_in, const int* in_sizes, int n_in,
                              void* d_out, int out_size) {
    const float* q = (const float*)d_in[0];
    const float* k = (const float*)d_in[1];
    const float* v = (const float*)d_in[2];
    float* out = (float*)d_out;

    cudaFuncSetAttribute(flash_kernel, cudaFuncAttributeMaxDynamicSharedMemorySize, SMEM_BYTES);

    zero_vsum_kernel<<<1, BATCH * DIM>>>();
    vprep_kernel<<<dim3(NK / 128, BATCH), 256>>>(v);
    normalize_kernel<<<(2 * BATCH * NQ) / 8, 256>>>(q, k);
    flash_kernel<<<dim3(NQ / BM, BATCH), THREADS, SMEM_BYTES>>>(out);
}